// round 7
// baseline (speedup 1.0000x reference)
#include <cuda_runtime.h>
#include <cuda_bf16.h>

#define BCH   10
#define HH    320
#define WW    1024
#define PTS   500
#define DENSE 2000
#define KMEAN 10
#define NPTS  (BCH * PTS)
#define CHUNKS (DENSE / 4)      // 500 int4 chunks per point

// Window: by in [-7,7] (15 rows), bx in [-11,11] (23 cols), padded to 32 cols.
#define WROWS 15
#define WCOLS 23
#define HSLOTS (WROWS * 32)     // 480

// One CTA (128 threads) per point. Block-cooperative histogram build
// (4 chunks/lane -> 8 independent LDG.128 in flight per lane), then warp 0
// runs the weighted k-means over the <=345 occupied window values.
__global__ __launch_bounds__(128, 8)
void rsbsp_kernel(const float* __restrict__ disp,
                  const float* __restrict__ fore,
                  const int*   __restrict__ cxs,
                  const int*   __restrict__ cys,
                  const int*   __restrict__ bxs,
                  const int*   __restrict__ bys,
                  float*       __restrict__ out)
{
    __shared__ int hist[HSLOTS];
    __shared__ int s_valid;

    const int n    = blockIdx.x;
    const int tid  = threadIdx.x;
    const int lane = tid & 31;

    const int chan = n / PTS;
    const int cx   = cxs[n];
    const int cy   = cys[n];
    const float* dch = disp + (size_t)chan * (HH * WW);
    const int    base = (cy << 10) + cx;          // WW == 1024

    // ---- validity (warp 0): maxpool3x3(|sobel_x(forepred)|)(cy,cx) > 3.1
    //      && disp(cy,cx) > 0.007.  Centers >= 11 px from all borders.
    if (tid < 32) {
        const float* fch = fore + (size_t)chan * (HH * WW);
        float g = 0.0f;
        if (lane < 9) {
            const int dy = lane / 3 - 1;
            const int dx = lane % 3 - 1;
            const float* p = fch + (size_t)(cy + dy - 1) * WW + (cx + dx);
            const float a = p[1]  + 2.0f * p[WW + 1] + p[2 * WW + 1];
            const float b = p[-1] + 2.0f * p[WW - 1] + p[2 * WW - 1];
            g = fabsf(a - b);
        }
        #pragma unroll
        for (int o = 16; o; o >>= 1) g = fmaxf(g, __shfl_xor_sync(0xFFFFFFFFu, g, o));
        if (lane == 0) {
            const float dC = dch[base];
            const int   v  = (g > 3.1f) && (dC > 0.007f);
            s_valid = v;
            if (!v) { out[2 * n] = 0.0f; out[2 * n + 1] = 0.0f; }
        }
    }
    // zero histogram while validity is in flight
    #pragma unroll
    for (int k = 0; k < 4; k++) {
        const int s = tid + (k << 7);
        if (s < HSLOTS) hist[s] = 0;
    }
    __syncthreads();
    if (!s_valid) return;        // ~75% of blocks retire here

    // ---- block-cooperative histogram of the 2000 samples ------------------
    const int4* bx4p = (const int4*)(bxs + (size_t)n * DENSE);
    const int4* by4p = (const int4*)(bys + (size_t)n * DENSE);

    #pragma unroll
    for (int k = 0; k < 4; k++) {
        const int  c     = tid + (k << 7);
        const bool valid = (k < 3) || (c < CHUNKS);  // 384 < 500; k=3: tid < 116
        if (valid) {
            const int4 b4 = bx4p[c];
            const int4 y4 = by4p[c];
            // slot = (y+7)*32 + (x+11) = y*32 + x + 235
            atomicAdd(&hist[(y4.x << 5) + b4.x + 235], 1);
            atomicAdd(&hist[(y4.y << 5) + b4.y + 235], 1);
            atomicAdd(&hist[(y4.z << 5) + b4.z + 235], 1);
            atomicAdd(&hist[(y4.w << 5) + b4.w + 235], 1);
        }
    }
    __syncthreads();
    if (tid >= 32) return;       // warp 0 finishes the point

    // ---- warp 0: weighted stats over the 15x23 window ---------------------
    float val [WROWS];
    float prod[WROWS];
    float cntf[WROWS];
    float mx = -1e30f, mn = 1e30f, stot = 0.0f;
    #pragma unroll
    for (int r = 0; r < WROWS; r++) {
        const int   cnt = hist[lane + (r << 5)];
        const float v   = (lane < WCOLS)
                        ? dch[base + (r - 7) * WW + (lane - 11)]   // coalesced row
                        : 0.0f;
        const float cf  = (float)cnt;
        val[r]  = v;
        cntf[r] = cf;
        prod[r] = v * cf;
        stot   += prod[r];
        if (cnt > 0) { mx = fmaxf(mx, v); mn = fminf(mn, v); }
    }
    #pragma unroll
    for (int o = 16; o; o >>= 1) {
        mx   = fmaxf(mx, __shfl_xor_sync(0xFFFFFFFFu, mx, o));
        mn   = fminf(mn, __shfl_xor_sync(0xFFFFFFFFu, mn, o));
        stot +=          __shfl_xor_sync(0xFFFFFFFFu, stot, o);
    }

    // ---- weighted 2-cluster 1-D k-means over <=345 unique values ----------
    // kL > kS => |s-kL|<=|s-kS| <=> s >= (kL+kS)/2 (midpoint tie -> large,
    // matching dl<=ds). Threshold acts on val only, so weighted sums equal the
    // per-sample sums exactly (same partition). Bitwise fixed point => the
    // remaining reference iterations are no-ops -> exact early exit.
    float kL = mx, kS = mn;
    float lastCnt = 0.0f;
    #pragma unroll 1
    for (int it = 0; it < KMEAN; it++) {
        const float mid = 0.5f * (kL + kS);
        float sumL = 0.0f, cntL = 0.0f;
        #pragma unroll
        for (int r = 0; r < WROWS; r++) {
            if (val[r] >= mid) { sumL += prod[r]; cntL += cntf[r]; }
        }
        #pragma unroll
        for (int o = 16; o; o >>= 1) {
            sumL += __shfl_xor_sync(0xFFFFFFFFu, sumL, o);
            cntL += __shfl_xor_sync(0xFFFFFFFFu, cntL, o);
        }
        const float nkL = __fdividef(sumL, cntL);
        const float nkS = __fdividef(stot - sumL, (float)DENSE - cntL);
        lastCnt = cntL;
        const bool conv = (nkL == kL) && (nkS == kS);
        kL = nkL; kS = nkS;
        if (conv) break;
    }

    const bool keep = ((kL - kS) > 0.005f) && (lastCnt > 5.0f);
    if (lane == 0) {
        const float kf = keep ? 1.0f : 0.0f;
        out[2 * n]     = kL * kf;
        out[2 * n + 1] = kS * kf;
    }
}

extern "C" void kernel_launch(void* const* d_in, const int* in_sizes, int n_in,
                              void* d_out, int out_size)
{
    const float* disp = (const float*)d_in[0];
    const float* fore = (const float*)d_in[1];
    const int*   cxs  = (const int*)  d_in[2];
    const int*   cys  = (const int*)  d_in[3];
    const int*   bxs  = (const int*)  d_in[4];
    const int*   bys  = (const int*)  d_in[5];
    float*       out  = (float*)d_out;

    rsbsp_kernel<<<NPTS, 128>>>(disp, fore, cxs, cys, bxs, bys, out);
}

// round 8
// speedup vs baseline: 1.1565x; 1.1565x over previous
#include <cuda_runtime.h>
#include <cuda_bf16.h>

#define BCH   10
#define HH    320
#define WW    1024
#define PTS   500
#define DENSE 2000
#define KMEAN 10
#define NPTS  (BCH * PTS)
#define CHUNKS (DENSE / 4)      // 500 int4 chunks per point

// Window: by in [-7,7] (15 rows), bx in [-11,11] (23 cols), padded to 32 cols.
#define WROWS 15
#define WCOLS 23
#define HSLOTS (WROWS * 32)     // 480

// One warp per point (round-6 structure), occupancy 8, with speculative
// front-loading of the first 2 bx/by chunk-groups to put DRAM loads in
// flight before the validity branch resolves.
__global__ __launch_bounds__(128, 8)
void rsbsp_kernel(const float* __restrict__ disp,
                  const float* __restrict__ fore,
                  const int*   __restrict__ cxs,
                  const int*   __restrict__ cys,
                  const int*   __restrict__ bxs,
                  const int*   __restrict__ bys,
                  float*       __restrict__ out)
{
    __shared__ int hist[4][HSLOTS];

    const int gwarp = (blockIdx.x * 128 + threadIdx.x) >> 5;
    const int wid   = (threadIdx.x >> 5);
    const int lane  = threadIdx.x & 31;
    if (gwarp >= NPTS) return;

    const int n    = gwarp;
    const int chan = n / PTS;
    const int cx   = cxs[n];
    const int cy   = cys[n];
    const float* dch = disp + (size_t)chan * (HH * WW);
    const float* fch = fore + (size_t)chan * (HH * WW);
    const int    base = (cy << 10) + cx;          // WW == 1024

    // ---- speculative bx/by loads (chunk groups 0 and 1) -------------------
    // Issued before validity resolves so DRAM latency overlaps the validity
    // L2 loads. Invalid warps waste 2KB/point of bandwidth (headroom exists).
    const int4* bx4p = (const int4*)(bxs + (size_t)n * DENSE);
    const int4* by4p = (const int4*)(bys + (size_t)n * DENSE);
    const int4 sb0 = bx4p[lane];        const int4 sy0 = by4p[lane];
    const int4 sb1 = bx4p[lane + 32];   const int4 sy1 = by4p[lane + 32];

    // ---- validity loads (in flight with the above) ------------------------
    float g = 0.0f;
    if (lane < 9) {
        const int dy = lane / 3 - 1;
        const int dx = lane % 3 - 1;
        const float* p = fch + (size_t)(cy + dy - 1) * WW + (cx + dx);
        const float a = p[1]  + 2.0f * p[WW + 1] + p[2 * WW + 1];
        const float b = p[-1] + 2.0f * p[WW - 1] + p[2 * WW - 1];
        g = fabsf(a - b);
    }
    const float dC = dch[base];

    // ---- zero histogram (independent STS, overlaps loads) -----------------
    int* h = hist[wid];
    #pragma unroll
    for (int r = 0; r < WROWS; r++) h[lane + (r << 5)] = 0;
    __syncwarp();

    // ---- consume speculative chunks (frees the int4 regs pre-branch) ------
    // slot = (y+7)*32 + (x+11) = y*32 + x + 235
    atomicAdd(&h[(sy0.x << 5) + sb0.x + 235], 1);
    atomicAdd(&h[(sy0.y << 5) + sb0.y + 235], 1);
    atomicAdd(&h[(sy0.z << 5) + sb0.z + 235], 1);
    atomicAdd(&h[(sy0.w << 5) + sb0.w + 235], 1);
    atomicAdd(&h[(sy1.x << 5) + sb1.x + 235], 1);
    atomicAdd(&h[(sy1.y << 5) + sb1.y + 235], 1);
    atomicAdd(&h[(sy1.z << 5) + sb1.z + 235], 1);
    atomicAdd(&h[(sy1.w << 5) + sb1.w + 235], 1);

    // ---- validity reduce + early exit -------------------------------------
    // maxpool3x3(|sobel_x(forepred)|)(cy,cx) > 3.1 && disp(cy,cx) > 0.007.
    // Centers are >= 11 px from all borders (zeroArea never reached).
    #pragma unroll
    for (int o = 16; o; o >>= 1) g = fmaxf(g, __shfl_xor_sync(0xFFFFFFFFu, g, o));
    if (!((g > 3.1f) && (dC > 0.007f))) {
        if (lane == 0) { out[2 * n] = 0.0f; out[2 * n + 1] = 0.0f; }
        return;
    }

    // ---- remaining chunk groups 2..15 -------------------------------------
    #pragma unroll 7
    for (int k = 2; k < 16; k++) {
        const int  c     = lane + (k << 5);
        const bool valid = (k < 15) || (c < CHUNKS);   // compile-time true k<15
        if (valid) {
            const int4 b4 = bx4p[c];
            const int4 y4 = by4p[c];
            atomicAdd(&h[(y4.x << 5) + b4.x + 235], 1);
            atomicAdd(&h[(y4.y << 5) + b4.y + 235], 1);
            atomicAdd(&h[(y4.z << 5) + b4.z + 235], 1);
            atomicAdd(&h[(y4.w << 5) + b4.w + 235], 1);
        }
    }
    __syncwarp();

    // ---- weighted stats over the 15x23 window -----------------------------
    float val [WROWS];
    float prod[WROWS];
    float cntf[WROWS];
    float mx = -1e30f, mn = 1e30f, stot = 0.0f;
    #pragma unroll
    for (int r = 0; r < WROWS; r++) {
        const int   cnt = h[lane + (r << 5)];
        const float v   = (lane < WCOLS)
                        ? dch[base + (r - 7) * WW + (lane - 11)]   // coalesced row
                        : 0.0f;
        const float cf  = (float)cnt;
        val[r]  = v;
        cntf[r] = cf;
        prod[r] = v * cf;
        stot   += prod[r];
        if (cnt > 0) { mx = fmaxf(mx, v); mn = fminf(mn, v); }
    }
    #pragma unroll
    for (int o = 16; o; o >>= 1) {
        mx   = fmaxf(mx, __shfl_xor_sync(0xFFFFFFFFu, mx, o));
        mn   = fminf(mn, __shfl_xor_sync(0xFFFFFFFFu, mn, o));
        stot +=          __shfl_xor_sync(0xFFFFFFFFu, stot, o);
    }

    // ---- weighted 2-cluster 1-D k-means over <=345 unique values ----------
    // kL > kS => |s-kL|<=|s-kS| <=> s >= (kL+kS)/2 (midpoint tie -> large,
    // matching dl<=ds). Threshold acts on val only, so weighted sums equal the
    // per-sample sums exactly (same partition). Bitwise fixed point => the
    // remaining reference iterations are no-ops -> exact early exit.
    float kL = mx, kS = mn;
    float lastCnt = 0.0f;
    #pragma unroll 1
    for (int it = 0; it < KMEAN; it++) {
        const float mid = 0.5f * (kL + kS);
        float sumL = 0.0f, cntL = 0.0f;
        #pragma unroll
        for (int r = 0; r < WROWS; r++) {
            if (val[r] >= mid) { sumL += prod[r]; cntL += cntf[r]; }
        }
        #pragma unroll
        for (int o = 16; o; o >>= 1) {
            sumL += __shfl_xor_sync(0xFFFFFFFFu, sumL, o);
            cntL += __shfl_xor_sync(0xFFFFFFFFu, cntL, o);
        }
        const float nkL = __fdividef(sumL, cntL);
        const float nkS = __fdividef(stot - sumL, (float)DENSE - cntL);
        lastCnt = cntL;
        const bool conv = (nkL == kL) && (nkS == kS);
        kL = nkL; kS = nkS;
        if (conv) break;
    }

    const bool keep = ((kL - kS) > 0.005f) && (lastCnt > 5.0f);
    if (lane == 0) {
        const float kf = keep ? 1.0f : 0.0f;
        out[2 * n]     = kL * kf;
        out[2 * n + 1] = kS * kf;
    }
}

extern "C" void kernel_launch(void* const* d_in, const int* in_sizes, int n_in,
                              void* d_out, int out_size)
{
    const float* disp = (const float*)d_in[0];
    const float* fore = (const float*)d_in[1];
    const int*   cxs  = (const int*)  d_in[2];
    const int*   cys  = (const int*)  d_in[3];
    const int*   bxs  = (const int*)  d_in[4];
    const int*   bys  = (const int*)  d_in[5];
    float*       out  = (float*)d_out;

    const int threads = 128;                       // 4 warps = 4 points / CTA
    const int blocks  = (NPTS * 32 + threads - 1) / threads;   // 1250
    rsbsp_kernel<<<blocks, threads>>>(disp, fore, cxs, cys, bxs, bys, out);
}

// round 9
// speedup vs baseline: 1.1875x; 1.0268x over previous
#include <cuda_runtime.h>
#include <cuda_bf16.h>

#define BCH   10
#define HH    320
#define WW    1024
#define PTS   500
#define DENSE 2000
#define KMEAN 10
#define NPTS  (BCH * PTS)
#define CHUNKS (DENSE / 4)      // 500 int4 chunks per point

// Window: by in [-7,7] (15 rows), bx in [-11,11] (23 cols), padded to 32 cols.
#define WROWS 15
#define WCOLS 23
#define HSLOTS (WROWS * 32)     // 480

// ONE WARP PER CTA, one point per warp. CTA retires the moment its warp
// exits -> invalid points (75%) free their slot immediately and the HW
// scheduler backfills. 32 CTAs/SM at 64 regs => 4736 points resident at t=0.
__global__ __launch_bounds__(32, 32)
void rsbsp_kernel(const float* __restrict__ disp,
                  const float* __restrict__ fore,
                  const int*   __restrict__ cxs,
                  const int*   __restrict__ cys,
                  const int*   __restrict__ bxs,
                  const int*   __restrict__ bys,
                  float*       __restrict__ out)
{
    __shared__ int hist[HSLOTS];

    const int n    = blockIdx.x;
    const int lane = threadIdx.x;

    const int chan = n / PTS;
    const int cx   = cxs[n];
    const int cy   = cys[n];
    const float* dch = disp + (size_t)chan * (HH * WW);
    const float* fch = fore + (size_t)chan * (HH * WW);
    const int    base = (cy << 10) + cx;          // WW == 1024

    // ---- validity: maxpool3x3(|sobel_x(forepred)|)(cy,cx) > 3.1
    //      && disp(cy,cx) > 0.007.  Centers >= 11 px from all borders.
    float g = 0.0f;
    if (lane < 9) {
        const int dy = lane / 3 - 1;
        const int dx = lane % 3 - 1;
        const float* p = fch + (size_t)(cy + dy - 1) * WW + (cx + dx);
        const float a = p[1]  + 2.0f * p[WW + 1] + p[2 * WW + 1];
        const float b = p[-1] + 2.0f * p[WW - 1] + p[2 * WW - 1];
        g = fabsf(a - b);
    }
    const float dC = dch[base];

    // zero histogram while the validity loads are in flight
    #pragma unroll
    for (int r = 0; r < WROWS; r++) hist[lane + (r << 5)] = 0;

    #pragma unroll
    for (int o = 16; o; o >>= 1) g = fmaxf(g, __shfl_xor_sync(0xFFFFFFFFu, g, o));
    if (!((g > 3.1f) && (dC > 0.007f))) {
        if (lane == 0) { out[2 * n] = 0.0f; out[2 * n + 1] = 0.0f; }
        return;                                   // CTA slot freed immediately
    }
    __syncwarp();

    // ---- histogram of the 2000 samples over the 15x23 window --------------
    const int4* bx4p = (const int4*)(bxs + (size_t)n * DENSE);
    const int4* by4p = (const int4*)(bys + (size_t)n * DENSE);

    #pragma unroll 8
    for (int k = 0; k < 16; k++) {
        const int  c     = lane + (k << 5);
        const bool valid = (k < 15) || (c < CHUNKS);   // compile-time true k<15
        if (valid) {
            const int4 b4 = bx4p[c];
            const int4 y4 = by4p[c];
            // slot = (y+7)*32 + (x+11) = y*32 + x + 235
            atomicAdd(&hist[(y4.x << 5) + b4.x + 235], 1);
            atomicAdd(&hist[(y4.y << 5) + b4.y + 235], 1);
            atomicAdd(&hist[(y4.z << 5) + b4.z + 235], 1);
            atomicAdd(&hist[(y4.w << 5) + b4.w + 235], 1);
        }
    }
    __syncwarp();

    // ---- weighted stats over the 15x23 window -----------------------------
    float val [WROWS];
    float prod[WROWS];
    float cntf[WROWS];
    float mx = -1e30f, mn = 1e30f, stot = 0.0f;
    #pragma unroll
    for (int r = 0; r < WROWS; r++) {
        const int   cnt = hist[lane + (r << 5)];
        const float v   = (lane < WCOLS)
                        ? dch[base + (r - 7) * WW + (lane - 11)]   // coalesced row
                        : 0.0f;
        const float cf  = (float)cnt;
        val[r]  = v;
        cntf[r] = cf;
        prod[r] = v * cf;
        stot   += prod[r];
        if (cnt > 0) { mx = fmaxf(mx, v); mn = fminf(mn, v); }
    }
    #pragma unroll
    for (int o = 16; o; o >>= 1) {
        mx   = fmaxf(mx, __shfl_xor_sync(0xFFFFFFFFu, mx, o));
        mn   = fminf(mn, __shfl_xor_sync(0xFFFFFFFFu, mn, o));
        stot +=          __shfl_xor_sync(0xFFFFFFFFu, stot, o);
    }

    // ---- weighted 2-cluster 1-D k-means over <=345 unique values ----------
    // kL > kS => |s-kL|<=|s-kS| <=> s >= (kL+kS)/2 (midpoint tie -> large,
    // matching dl<=ds). Threshold acts on val only, so weighted sums equal the
    // per-sample sums exactly (same partition). Bitwise fixed point => the
    // remaining reference iterations are no-ops -> exact early exit.
    float kL = mx, kS = mn;
    float lastCnt = 0.0f;
    #pragma unroll 1
    for (int it = 0; it < KMEAN; it++) {
        const float mid = 0.5f * (kL + kS);
        float sumL = 0.0f, cntL = 0.0f;
        #pragma unroll
        for (int r = 0; r < WROWS; r++) {
            if (val[r] >= mid) { sumL += prod[r]; cntL += cntf[r]; }
        }
        #pragma unroll
        for (int o = 16; o; o >>= 1) {
            sumL += __shfl_xor_sync(0xFFFFFFFFu, sumL, o);
            cntL += __shfl_xor_sync(0xFFFFFFFFu, cntL, o);
        }
        const float nkL = __fdividef(sumL, cntL);
        const float nkS = __fdividef(stot - sumL, (float)DENSE - cntL);
        lastCnt = cntL;
        const bool conv = (nkL == kL) && (nkS == kS);
        kL = nkL; kS = nkS;
        if (conv) break;
    }

    const bool keep = ((kL - kS) > 0.005f) && (lastCnt > 5.0f);
    if (lane == 0) {
        const float kf = keep ? 1.0f : 0.0f;
        out[2 * n]     = kL * kf;
        out[2 * n + 1] = kS * kf;
    }
}

extern "C" void kernel_launch(void* const* d_in, const int* in_sizes, int n_in,
                              void* d_out, int out_size)
{
    const float* disp = (const float*)d_in[0];
    const float* fore = (const float*)d_in[1];
    const int*   cxs  = (const int*)  d_in[2];
    const int*   cys  = (const int*)  d_in[3];
    const int*   bxs  = (const int*)  d_in[4];
    const int*   bys  = (const int*)  d_in[5];
    float*       out  = (float*)d_out;

    rsbsp_kernel<<<NPTS, 32>>>(disp, fore, cxs, cys, bxs, bys, out);
}